// round 5
// baseline (speedup 1.0000x reference)
#include <cuda_runtime.h>
#include <math.h>

// Problem constants
#define B_  32
#define DM  512
#define S_  64
#define L_  4096
#define KSPLIT 16          // split-K factor for the NT GEMM (K=4096 -> 16 x 256)

// ---------------------------------------------------------------------------
// Scratch (device globals - no allocation allowed)
// ---------------------------------------------------------------------------
__device__ float g_braw [(size_t)B_ * 3 * S_ * L_];          // [B,192,4096] pre-conv
__device__ float g_cm   [(size_t)B_ * S_ * L_];              // [B,64,4096]  conv'd C
__device__ float g_ab   [(size_t)B_ * S_ * L_];              // [B,64,4096]  softmax(dt)*Bm
__device__ float g_hpart[(size_t)KSPLIT * DM * B_ * S_];     // [16,512,2048] split-K partials
__device__ float g_hcb  [(size_t)DM * B_ * S_];              // [512,2048]  h in [c][b*64+s]
__device__ float g_hz   [(size_t)2 * DM * B_ * S_];          // [1024,2048]
__device__ float g_hg   [(size_t)DM * B_ * S_];              // [512,2048]

// ---------------------------------------------------------------------------
// NN GEMM: C[M,N] = A[M,K] @ B[K,N] (+bias[M])
// Tile 64(M) x 128(N), K-chunk 16, 256 threads, 4x8 microtile,
// register prefetch of next K-chunk.
// EPI==0: C row-major with ldc. EPI==1: scatter col n -> (b=n>>6, s=n&63),
//         addr = b*32768 + row*64 + s   (ho written straight into d_out).
// Requires: M%64==0 (grid), N%128==0, K%16==0, lda/ldb %4==0.
// ---------------------------------------------------------------------------
template <int EPI>
__global__ void __launch_bounds__(256) gemm_nn(
    const float* __restrict__ A, long long sA, int lda,
    const float* __restrict__ B, long long sB, int ldb,
    float* __restrict__ C, long long sC, int ldc,
    const float* __restrict__ bias, int K)
{
    __shared__ float As[16][68];    // [k][m], padded (68%4==0 keeps float4 align)
    __shared__ float Bs[16][128];   // [k][n]

    const int bz = blockIdx.z;
    A += (size_t)bz * sA;
    B += (size_t)bz * sB;
    C += (size_t)bz * sC;

    const int m0 = blockIdx.y * 64;
    const int n0 = blockIdx.x * 128;
    const int t  = threadIdx.x;
    const int tx = t & 15, ty = t >> 4;

    const int ar = t >> 2;            // 0..63 : A row within tile
    const int ak = (t & 3) << 2;      // 0,4,8,12
    const int bk = t >> 4;            // 0..15 : B k-row
    const int bn = (t & 15) << 3;     // 0..120

    const float* Aptr = A + (size_t)(m0 + ar) * lda + ak;
    const float* Bptr = B + (size_t)bk * ldb + n0 + bn;

    float4 a_pf  = *(const float4*)Aptr;
    float4 b0_pf = *(const float4*)Bptr;
    float4 b1_pf = *(const float4*)(Bptr + 4);

    float acc[4][8] = {};

    // stage first chunk
    As[ak + 0][ar] = a_pf.x; As[ak + 1][ar] = a_pf.y;
    As[ak + 2][ar] = a_pf.z; As[ak + 3][ar] = a_pf.w;
    *(float4*)&Bs[bk][bn]     = b0_pf;
    *(float4*)&Bs[bk][bn + 4] = b1_pf;
    __syncthreads();

    const int nk = K >> 4;
    for (int it = 1; it < nk; it++) {
        Aptr += 16;
        Bptr += (size_t)16 * ldb;
        a_pf  = *(const float4*)Aptr;          // prefetch next chunk
        b0_pf = *(const float4*)Bptr;
        b1_pf = *(const float4*)(Bptr + 4);

#pragma unroll
        for (int kk = 0; kk < 16; kk++) {
            float4 a  = *(const float4*)&As[kk][ty * 4];
            float4 b0 = *(const float4*)&Bs[kk][tx * 8];
            float4 b1 = *(const float4*)&Bs[kk][tx * 8 + 4];
            acc[0][0] += a.x*b0.x; acc[0][1] += a.x*b0.y; acc[0][2] += a.x*b0.z; acc[0][3] += a.x*b0.w;
            acc[0][4] += a.x*b1.x; acc[0][5] += a.x*b1.y; acc[0][6] += a.x*b1.z; acc[0][7] += a.x*b1.w;
            acc[1][0] += a.y*b0.x; acc[1][1] += a.y*b0.y; acc[1][2] += a.y*b0.z; acc[1][3] += a.y*b0.w;
            acc[1][4] += a.y*b1.x; acc[1][5] += a.y*b1.y; acc[1][6] += a.y*b1.z; acc[1][7] += a.y*b1.w;
            acc[2][0] += a.z*b0.x; acc[2][1] += a.z*b0.y; acc[2][2] += a.z*b0.z; acc[2][3] += a.z*b0.w;
            acc[2][4] += a.z*b1.x; acc[2][5] += a.z*b1.y; acc[2][6] += a.z*b1.z; acc[2][7] += a.z*b1.w;
            acc[3][0] += a.w*b0.x; acc[3][1] += a.w*b0.y; acc[3][2] += a.w*b0.z; acc[3][3] += a.w*b0.w;
            acc[3][4] += a.w*b1.x; acc[3][5] += a.w*b1.y; acc[3][6] += a.w*b1.z; acc[3][7] += a.w*b1.w;
        }
        __syncthreads();
        As[ak + 0][ar] = a_pf.x; As[ak + 1][ar] = a_pf.y;
        As[ak + 2][ar] = a_pf.z; As[ak + 3][ar] = a_pf.w;
        *(float4*)&Bs[bk][bn]     = b0_pf;
        *(float4*)&Bs[bk][bn + 4] = b1_pf;
        __syncthreads();
    }
    // last chunk
#pragma unroll
    for (int kk = 0; kk < 16; kk++) {
        float4 a  = *(const float4*)&As[kk][ty * 4];
        float4 b0 = *(const float4*)&Bs[kk][tx * 8];
        float4 b1 = *(const float4*)&Bs[kk][tx * 8 + 4];
        acc[0][0] += a.x*b0.x; acc[0][1] += a.x*b0.y; acc[0][2] += a.x*b0.z; acc[0][3] += a.x*b0.w;
        acc[0][4] += a.x*b1.x; acc[0][5] += a.x*b1.y; acc[0][6] += a.x*b1.z; acc[0][7] += a.x*b1.w;
        acc[1][0] += a.y*b0.x; acc[1][1] += a.y*b0.y; acc[1][2] += a.y*b0.z; acc[1][3] += a.y*b0.w;
        acc[1][4] += a.y*b1.x; acc[1][5] += a.y*b1.y; acc[1][6] += a.y*b1.z; acc[1][7] += a.y*b1.w;
        acc[2][0] += a.z*b0.x; acc[2][1] += a.z*b0.y; acc[2][2] += a.z*b0.z; acc[2][3] += a.z*b0.w;
        acc[2][4] += a.z*b1.x; acc[2][5] += a.z*b1.y; acc[2][6] += a.z*b1.z; acc[2][7] += a.z*b1.w;
        acc[3][0] += a.w*b0.x; acc[3][1] += a.w*b0.y; acc[3][2] += a.w*b0.z; acc[3][3] += a.w*b0.w;
        acc[3][4] += a.w*b1.x; acc[3][5] += a.w*b1.y; acc[3][6] += a.w*b1.z; acc[3][7] += a.w*b1.w;
    }

#pragma unroll
    for (int i = 0; i < 4; i++) {
        const int row = m0 + ty * 4 + i;
        const float bi = bias ? bias[row] : 0.0f;
        float4 o0, o1;
        o0.x = acc[i][0] + bi; o0.y = acc[i][1] + bi; o0.z = acc[i][2] + bi; o0.w = acc[i][3] + bi;
        o1.x = acc[i][4] + bi; o1.y = acc[i][5] + bi; o1.z = acc[i][6] + bi; o1.w = acc[i][7] + bi;
        if (EPI == 0) {
            float* cp = C + (size_t)row * ldc + n0 + tx * 8;
            *(float4*)cp       = o0;
            *(float4*)(cp + 4) = o1;
        } else {
            const int n = n0 + tx * 8;
            float* cp = C + (size_t)(n >> 6) * (DM * S_) + (size_t)row * S_ + (n & 63);
            *(float4*)cp       = o0;
            *(float4*)(cp + 4) = o1;
        }
    }
}

// ---------------------------------------------------------------------------
// NT GEMM with split-K: C_part[kx][M, 2048-col] = A[M,Kseg] @ B[N,Kseg]^T
// A [M,K] row-major (K contig), B [N,K] row-major (K contig). N = 64.
// Tile 128(M) x 64(N), K-chunk 16, 256 threads, 8x4 microtile, prefetch.
// Output: C + kx*1048576 + bz*64 ;  C[row*2048 + n]   (h in [c][b*64+s] layout)
// ---------------------------------------------------------------------------
__global__ void __launch_bounds__(256) gemm_nt_splitk(
    const float* __restrict__ A, long long sA, int lda,
    const float* __restrict__ B, long long sB, int ldb,
    float* __restrict__ C, int Ksub)
{
    __shared__ float As[16][132];   // [k][m]
    __shared__ float Bs[16][68];    // [k][n]

    const int kx = blockIdx.x;
    const int m0 = blockIdx.y * 128;
    const int bz = blockIdx.z;
    A += (size_t)bz * sA + (size_t)kx * Ksub;
    B += (size_t)bz * sB + (size_t)kx * Ksub;
    C += (size_t)kx * ((size_t)DM * B_ * S_) + (size_t)bz * S_;

    const int t  = threadIdx.x;
    const int tx = t & 15, ty = t >> 4;

    const int ar  = t >> 1;          // 0..127
    const int akq = (t & 1) << 3;    // 0, 8
    const int br  = t >> 2;          // 0..63
    const int bkq = (t & 3) << 2;    // 0,4,8,12

    const float* Aptr = A + (size_t)(m0 + ar) * lda + akq;
    const float* Bptr = B + (size_t)br * ldb + bkq;

    float4 a0_pf = *(const float4*)Aptr;
    float4 a1_pf = *(const float4*)(Aptr + 4);
    float4 b_pf  = *(const float4*)Bptr;

    float acc[8][4] = {};

    As[akq + 0][ar] = a0_pf.x; As[akq + 1][ar] = a0_pf.y;
    As[akq + 2][ar] = a0_pf.z; As[akq + 3][ar] = a0_pf.w;
    As[akq + 4][ar] = a1_pf.x; As[akq + 5][ar] = a1_pf.y;
    As[akq + 6][ar] = a1_pf.z; As[akq + 7][ar] = a1_pf.w;
    Bs[bkq + 0][br] = b_pf.x;  Bs[bkq + 1][br] = b_pf.y;
    Bs[bkq + 2][br] = b_pf.z;  Bs[bkq + 3][br] = b_pf.w;
    __syncthreads();

    const int nk = Ksub >> 4;
    for (int it = 1; it < nk; it++) {
        Aptr += 16;
        Bptr += 16;
        a0_pf = *(const float4*)Aptr;
        a1_pf = *(const float4*)(Aptr + 4);
        b_pf  = *(const float4*)Bptr;

#pragma unroll
        for (int kk = 0; kk < 16; kk++) {
            float4 a0 = *(const float4*)&As[kk][ty * 8];
            float4 a1 = *(const float4*)&As[kk][ty * 8 + 4];
            float4 b  = *(const float4*)&Bs[kk][tx * 4];
            acc[0][0] += a0.x*b.x; acc[0][1] += a0.x*b.y; acc[0][2] += a0.x*b.z; acc[0][3] += a0.x*b.w;
            acc[1][0] += a0.y*b.x; acc[1][1] += a0.y*b.y; acc[1][2] += a0.y*b.z; acc[1][3] += a0.y*b.w;
            acc[2][0] += a0.z*b.x; acc[2][1] += a0.z*b.y; acc[2][2] += a0.z*b.z; acc[2][3] += a0.z*b.w;
            acc[3][0] += a0.w*b.x; acc[3][1] += a0.w*b.y; acc[3][2] += a0.w*b.z; acc[3][3] += a0.w*b.w;
            acc[4][0] += a1.x*b.x; acc[4][1] += a1.x*b.y; acc[4][2] += a1.x*b.z; acc[4][3] += a1.x*b.w;
            acc[5][0] += a1.y*b.x; acc[5][1] += a1.y*b.y; acc[5][2] += a1.y*b.z; acc[5][3] += a1.y*b.w;
            acc[6][0] += a1.z*b.x; acc[6][1] += a1.z*b.y; acc[6][2] += a1.z*b.z; acc[6][3] += a1.z*b.w;
            acc[7][0] += a1.w*b.x; acc[7][1] += a1.w*b.y; acc[7][2] += a1.w*b.z; acc[7][3] += a1.w*b.w;
        }
        __syncthreads();
        As[akq + 0][ar] = a0_pf.x; As[akq + 1][ar] = a0_pf.y;
        As[akq + 2][ar] = a0_pf.z; As[akq + 3][ar] = a0_pf.w;
        As[akq + 4][ar] = a1_pf.x; As[akq + 5][ar] = a1_pf.y;
        As[akq + 6][ar] = a1_pf.z; As[akq + 7][ar] = a1_pf.w;
        Bs[bkq + 0][br] = b_pf.x;  Bs[bkq + 1][br] = b_pf.y;
        Bs[bkq + 2][br] = b_pf.z;  Bs[bkq + 3][br] = b_pf.w;
        __syncthreads();
    }
#pragma unroll
    for (int kk = 0; kk < 16; kk++) {
        float4 a0 = *(const float4*)&As[kk][ty * 8];
        float4 a1 = *(const float4*)&As[kk][ty * 8 + 4];
        float4 b  = *(const float4*)&Bs[kk][tx * 4];
        acc[0][0] += a0.x*b.x; acc[0][1] += a0.x*b.y; acc[0][2] += a0.x*b.z; acc[0][3] += a0.x*b.w;
        acc[1][0] += a0.y*b.x; acc[1][1] += a0.y*b.y; acc[1][2] += a0.y*b.z; acc[1][3] += a0.y*b.w;
        acc[2][0] += a0.z*b.x; acc[2][1] += a0.z*b.y; acc[2][2] += a0.z*b.z; acc[2][3] += a0.z*b.w;
        acc[3][0] += a0.w*b.x; acc[3][1] += a0.w*b.y; acc[3][2] += a0.w*b.z; acc[3][3] += a0.w*b.w;
        acc[4][0] += a1.x*b.x; acc[4][1] += a1.x*b.y; acc[4][2] += a1.x*b.z; acc[4][3] += a1.x*b.w;
        acc[5][0] += a1.y*b.x; acc[5][1] += a1.y*b.y; acc[5][2] += a1.y*b.z; acc[5][3] += a1.y*b.w;
        acc[6][0] += a1.z*b.x; acc[6][1] += a1.z*b.y; acc[6][2] += a1.z*b.z; acc[6][3] += a1.z*b.w;
        acc[7][0] += a1.w*b.x; acc[7][1] += a1.w*b.y; acc[7][2] += a1.w*b.z; acc[7][3] += a1.w*b.w;
    }

#pragma unroll
    for (int i = 0; i < 8; i++) {
        const int row = m0 + ty * 8 + i;
        float4 o;
        o.x = acc[i][0]; o.y = acc[i][1]; o.z = acc[i][2]; o.w = acc[i][3];
        *(float4*)(C + (size_t)row * (B_ * S_) + tx * 4) = o;
    }
}

// ---------------------------------------------------------------------------
// Reduce split-K partials: h_cb = sum over 16 slabs of [512,2048]
// ---------------------------------------------------------------------------
__global__ void __launch_bounds__(256) reduce_splitk(
    const float4* __restrict__ in, float4* __restrict__ out)
{
    const int n4 = (DM * B_ * S_) / 4;  // 262144
    const int i = blockIdx.x * 256 + threadIdx.x;
    if (i >= n4) return;
    float4 s = in[i];
#pragma unroll
    for (int k = 1; k < KSPLIT; k++) {
        float4 v = in[i + (size_t)k * n4];
        s.x += v.x; s.y += v.y; s.z += v.z; s.w += v.w;
    }
    out[i] = s;
}

// ---------------------------------------------------------------------------
// Fused depthwise 3x3 conv + softmax + AB.  One block per (s, b).
// Processes channels dt(128+s), Bm(s), Cm(64+s) sequentially through one
// 16KB input-plane buffer. Softmax over the whole plane (A[s] cancels).
// Writes AB and Cm; Bm never hits memory.
// ---------------------------------------------------------------------------
__global__ void __launch_bounds__(256) conv_softmax_ab(
    const float* __restrict__ braw,
    const float* __restrict__ w_dw, const float* __restrict__ b_dw,
    float* __restrict__ cm, float* __restrict__ ab)
{
    __shared__ float sin[4096];
    __shared__ float red[256];

    const int s  = blockIdx.x;    // 0..63
    const int b  = blockIdx.y;    // 0..31
    const int tid = threadIdx.x;
    const size_t base = (size_t)b * (3 * S_ * L_);

    float r[16], p[16], w[9];

    // ---- pass 1: dt channel (128+s): conv -> softmax probs in p[] ----
    {
        const int ch = 128 + s;
        const float* ip = braw + base + (size_t)ch * 4096;
        for (int k = 0; k < 16; k++) sin[tid + k * 256] = ip[tid + k * 256];
#pragma unroll
        for (int j = 0; j < 9; j++) w[j] = w_dw[ch * 9 + j];
        const float bv = b_dw[ch];
        __syncthreads();

#pragma unroll
        for (int k = 0; k < 16; k++) {
            const int idx = k * 256 + tid;
            const int i = idx >> 6, j = idx & 63;
            float acc = bv;
#pragma unroll
            for (int di = 0; di < 3; di++) {
                const int ii = i + di - 1;
                if (ii < 0 || ii > 63) continue;
#pragma unroll
                for (int dj = 0; dj < 3; dj++) {
                    const int jj = j + dj - 1;
                    if (jj < 0 || jj > 63) continue;
                    acc += w[di * 3 + dj] * sin[(ii << 6) + jj];
                }
            }
            r[k] = acc;
        }
        // block max
        float mx = r[0];
#pragma unroll
        for (int k = 1; k < 16; k++) mx = fmaxf(mx, r[k]);
        red[tid] = mx; __syncthreads();
        for (int off = 128; off > 0; off >>= 1) {
            if (tid < off) red[tid] = fmaxf(red[tid], red[tid + off]);
            __syncthreads();
        }
        mx = red[0]; __syncthreads();
        // block sum
        float sum = 0.0f;
#pragma unroll
        for (int k = 0; k < 16; k++) { p[k] = expf(r[k] - mx); sum += p[k]; }
        red[tid] = sum; __syncthreads();
        for (int off = 128; off > 0; off >>= 1) {
            if (tid < off) red[tid] += red[tid + off];
            __syncthreads();
        }
        const float inv = 1.0f / red[0];
#pragma unroll
        for (int k = 0; k < 16; k++) p[k] *= inv;
        __syncthreads();   // everyone done with sin before reload
    }

    // ---- pass 2: Bm channel (s): conv -> AB = p * conv(Bm) ----
    {
        const int ch = s;
        const float* ip = braw + base + (size_t)ch * 4096;
        for (int k = 0; k < 16; k++) sin[tid + k * 256] = ip[tid + k * 256];
#pragma unroll
        for (int j = 0; j < 9; j++) w[j] = w_dw[ch * 9 + j];
        const float bv = b_dw[ch];
        __syncthreads();

        float* op = ab + (size_t)b * (S_ * L_) + (size_t)s * 4096;
#pragma unroll
        for (int k = 0; k < 16; k++) {
            const int idx = k * 256 + tid;
            const int i = idx >> 6, j = idx & 63;
            float acc = bv;
#pragma unroll
            for (int di = 0; di < 3; di++) {
                const int ii = i + di - 1;
                if (ii < 0 || ii > 63) continue;
#pragma unroll
                for (int dj = 0; dj < 3; dj++) {
                    const int jj = j + dj - 1;
                    if (jj < 0 || jj > 63) continue;
                    acc += w[di * 3 + dj] * sin[(ii << 6) + jj];
                }
            }
            op[idx] = p[k] * acc;
        }
        __syncthreads();
    }

    // ---- pass 3: Cm channel (64+s): conv -> cm ----
    {
        const int ch = 64 + s;
        const float* ip = braw + base + (size_t)ch * 4096;
        for (int k = 0; k < 16; k++) sin[tid + k * 256] = ip[tid + k * 256];
#pragma unroll
        for (int j = 0; j < 9; j++) w[j] = w_dw[ch * 9 + j];
        const float bv = b_dw[ch];
        __syncthreads();

        float* op = cm + (size_t)b * (S_ * L_) + (size_t)s * 4096;
#pragma unroll
        for (int k = 0; k < 16; k++) {
            const int idx = k * 256 + tid;
            const int i = idx >> 6, j = idx & 63;
            float acc = bv;
#pragma unroll
            for (int di = 0; di < 3; di++) {
                const int ii = i + di - 1;
                if (ii < 0 || ii > 63) continue;
#pragma unroll
                for (int dj = 0; dj < 3; dj++) {
                    const int jj = j + dj - 1;
                    if (jj < 0 || jj > 63) continue;
                    acc += w[di * 3 + dj] * sin[(ii << 6) + jj];
                }
            }
            op[idx] = acc;
        }
    }
}

// ---------------------------------------------------------------------------
// Gating on [o][b*64+s] layout:  hg = h1 * (z*sigmoid(z) + Dskip)
// h1 = hz[0:512], z = hz[512:1024]
// ---------------------------------------------------------------------------
__global__ void __launch_bounds__(256) gate_kernel(
    const float* __restrict__ hz, float* __restrict__ hg,
    const float* __restrict__ Dskip)
{
    const int total = DM * B_ * S_;   // 1048576
    const int i = blockIdx.x * 256 + threadIdx.x;
    if (i >= total) return;
    const float h1 = hz[i];
    const float z  = hz[i + total];
    const float sig = 1.0f / (1.0f + expf(-z));
    hg[i] = h1 * (z * sig + Dskip[0]);
}

// ---------------------------------------------------------------------------
// Host launch
// ---------------------------------------------------------------------------
extern "C" void kernel_launch(void* const* d_in, const int* in_sizes, int n_in,
                              void* d_out, int out_size)
{
    (void)in_sizes; (void)n_in; (void)out_size;

    const float* x      = (const float*)d_in[0];   // [32,512,4096]
    const float* w_bcdt = (const float*)d_in[1];   // [192,512]
    const float* b_bcdt = (const float*)d_in[2];   // [192]
    const float* w_dw   = (const float*)d_in[3];   // [192,1,3,3]
    const float* b_dw   = (const float*)d_in[4];   // [192]
    const float* w_hz   = (const float*)d_in[5];   // [1024,512]
    const float* b_hz   = (const float*)d_in[6];   // [1024]
    const float* w_out  = (const float*)d_in[7];   // [512,512]
    const float* b_out  = (const float*)d_in[8];   // [512]
    const float* Dskip  = (const float*)d_in[10];  // [1]  (A at [9] cancels in softmax)

    float* out = (float*)d_out;
    float* y   = out;                               // [32,512,4096]
    float* ho  = out + (size_t)B_ * DM * L_;        // [32,512,64]

    float *braw, *cm, *ab, *hpart, *hcb, *hz, *hg;
    cudaGetSymbolAddress((void**)&braw,  g_braw);
    cudaGetSymbolAddress((void**)&cm,    g_cm);
    cudaGetSymbolAddress((void**)&ab,    g_ab);
    cudaGetSymbolAddress((void**)&hpart, g_hpart);
    cudaGetSymbolAddress((void**)&hcb,   g_hcb);
    cudaGetSymbolAddress((void**)&hz,    g_hz);
    cudaGetSymbolAddress((void**)&hg,    g_hg);

    const dim3 blk(256);

    // 1) braw[b] = w_bcdt @ x[b] + b_bcdt        (M=192, N=4096, K=512, per-batch)
    gemm_nn<0><<<dim3(L_ / 128, 192 / 64, B_), blk>>>(
        w_bcdt, 0, DM,
        x, (long long)DM * L_, L_,
        braw, (long long)3 * S_ * L_, L_,
        b_bcdt, DM);

    // 2) fused dwconv + softmax + AB / Cm
    conv_softmax_ab<<<dim3(S_, B_), blk>>>(braw, w_dw, b_dw, cm, ab);

    // 3) split-K NT: hpart[kx] += x[b] @ AB[b]^T   (M=512, N=64, Kseg=256)
    gemm_nt_splitk<<<dim3(KSPLIT, DM / 128, B_), blk>>>(
        x, (long long)DM * L_, L_,
        ab, (long long)S_ * L_, L_,
        hpart, L_ / KSPLIT);

    // 4) reduce partials -> h_cb [512][2048]
    reduce_splitk<<<(DM * B_ * S_ / 4 + 255) / 256, blk>>>(
        (const float4*)hpart, (float4*)hcb);

    // 5) hz = w_hz @ h_cb + b_hz                 (M=1024, N=2048, K=512, single)
    gemm_nn<0><<<dim3(B_ * S_ / 128, 2 * DM / 64, 1), blk>>>(
        w_hz, 0, DM,
        hcb, 0, B_ * S_,
        hz, 0, B_ * S_,
        b_hz, DM);

    // 6) gating
    gate_kernel<<<(DM * B_ * S_ + 255) / 256, blk>>>(hz, hg, Dskip);

    // 7) ho = w_out @ hg + b_out, scattered into d_out [b][512][64]
    gemm_nn<1><<<dim3(B_ * S_ / 128, DM / 64, 1), blk>>>(
        w_out, 0, DM,
        hg, 0, B_ * S_,
        ho, 0, 0,
        b_out, DM);

    // 8) y[b] = ho[b] @ Cm[b]                    (M=512, N=4096, K=64, per-batch)
    gemm_nn<0><<<dim3(L_ / 128, DM / 64, B_), blk>>>(
        ho, (long long)DM * S_, S_,
        cm, (long long)S_ * L_, L_,
        y, (long long)DM * L_, L_,
        nullptr, S_);
}

// round 8
// speedup vs baseline: 1.9440x; 1.9440x over previous
#include <cuda_runtime.h>
#include <math.h>
#include <stdint.h>

// Problem constants
#define B_  32
#define DM  512
#define S_  64
#define L_  4096
#define KSPLIT3 4    // split-K for step 3 (K=4096 -> 4 x 1024)

// ---------------------------------------------------------------------------
// Scratch (device globals - no allocation allowed)
// ---------------------------------------------------------------------------
__device__ float g_braw [(size_t)B_ * 3 * S_ * L_];        // [B,192,4096] pre-conv
__device__ float g_cm   [(size_t)B_ * S_ * L_];            // [B,64,4096]  conv'd C [s][l]
__device__ float g_ab   [(size_t)B_ * S_ * L_];            // [B,64,4096]  softmax(dt)*Bm [s][l]
__device__ float g_hpart[(size_t)KSPLIT3 * DM * B_ * S_];  // [4,512,2048] split-K partials
__device__ float g_hcb  [(size_t)DM * B_ * S_];            // [512,2048]   h in [c][b*64+s]
__device__ float g_hz   [(size_t)2 * DM * B_ * S_];        // [1024,2048]
__device__ float g_hg   [(size_t)DM * B_ * S_];            // [512,2048]

// ===========================================================================
// TF32 warp-MMA GEMM (mma.sync m16n8k8 — baseline PTX, works on compute_103)
// ===========================================================================

static __device__ __forceinline__ uint32_t f2tf(float x) {
    uint32_t u;
    asm("cvt.rna.tf32.f32 %0, %1;" : "=r"(u) : "f"(x));
    return u;
}

static __device__ __forceinline__ void mma8(float* c, const uint32_t* a,
                                            uint32_t b0, uint32_t b1) {
    asm volatile(
        "mma.sync.aligned.m16n8k8.row.col.f32.tf32.tf32.f32 "
        "{%0,%1,%2,%3}, {%4,%5,%6,%7}, {%8,%9}, {%0,%1,%2,%3};"
        : "+f"(c[0]), "+f"(c[1]), "+f"(c[2]), "+f"(c[3])
        : "r"(a[0]), "r"(a[1]), "r"(a[2]), "r"(a[3]), "r"(b0), "r"(b1));
}

// smem tile layout: 32 words per row, word (row, k) stored at
//   row*32 + (k ^ ((row & 7) << 2))
// -> fragment LDS conflict-free; K-contig float4 staging conflict-free.
#define SWZ(row, k) (((row) << 5) + ((k) ^ (((row) & 7) << 2)))

// ---------------------------------------------------------------------------
// gemm_mma<NT, BT, KSP, EPI>:
//   C[M, N](tile 128 x NT) = A[M,K] . op(B)  in tf32, fp32 accum, +bias[row].
//   A: [Mtot, K] row-major (K contig), lda; rows >= Mtot are zero-padded.
//   BT=0: B is [N, K] row-major (K contig), ldb   (requires NT == 64)
//   BT=1: B is [K, N] row-major (N contig), ldb — transposed during staging
//         (requires NT == 128)
//   KSP: split-K segments; blockIdx.z = bz * KSP + kseg;
//        C += bz*sC + kseg*segStride.
//   EPI=0: C row-major (ldc).  EPI=1: col n scattered to (n>>6)*DM*S_+row*S_+(n&63).
// ---------------------------------------------------------------------------
template <int NT, bool BT, int KSP, int EPI>
__global__ void __launch_bounds__(256) gemm_mma(
    const float* __restrict__ A, long long sA, int lda,
    const float* __restrict__ B, long long sB, int ldb,
    float* __restrict__ C, long long sC, int ldc, long long segStride,
    const float* __restrict__ bias, int Mtot, int K)
{
    constexpr int MT = (NT == 128) ? 2 : 1;   // mma m-tiles per warp

    __shared__ uint32_t As[128 * 32];
    __shared__ uint32_t Bs[NT * 32];

    const int zz = blockIdx.z;
    const int bz = zz / KSP, kseg = zz % KSP;
    A += (size_t)bz * sA;
    B += (size_t)bz * sB;
    C += (size_t)bz * sC + (size_t)kseg * segStride;

    const int m0 = blockIdx.y * 128;
    const int n0 = blockIdx.x * NT;
    const int tid  = threadIdx.x;
    const int w    = tid >> 5;
    const int lane = tid & 31;
    const int gid  = lane >> 2;   // 0..7
    const int tig  = lane & 3;    // 0..3

    const int mBase = (NT == 128) ? ((w >> 1) * 32) : (w * 16);
    const int nBase = (NT == 128) ? ((w & 1) * 64) : 0;

    float acc[MT][8][4] = {};

    // A staging: thread -> (row ar, 16-float half ah), 4x STS.128 per chunk
    const int ar = tid >> 1;
    const int ah = (tid & 1) << 4;
    const bool avalid = (m0 + ar) < Mtot;

    const int Kseg = K / KSP;
    const int kbeg = kseg * Kseg;
    const int nch  = Kseg >> 5;

    for (int c = 0; c < nch; c++) {
        const int k0 = kbeg + (c << 5);

        // ---- stage A [128 rows x 32 k] ----
        {
            const float* ap = A + (size_t)(m0 + ar) * lda + k0 + ah;
#pragma unroll
            for (int j = 0; j < 4; j++) {
                float4 v = avalid ? *(const float4*)(ap + j * 4)
                                  : make_float4(0.f, 0.f, 0.f, 0.f);
                uint4 u;
                u.x = f2tf(v.x); u.y = f2tf(v.y); u.z = f2tf(v.z); u.w = f2tf(v.w);
                *(uint4*)&As[SWZ(ar, ah + j * 4)] = u;
            }
        }

        // ---- stage B [NT rows(n) x 32 k] ----
        if (BT) {
            // B[k][n] (n contig): transpose during staging. NT == 128.
            const int bk  = tid >> 3;          // 0..31
            const int bn0 = (tid & 7) << 4;    // 0..112
            const float* bp = B + (size_t)(k0 + bk) * ldb + n0 + bn0;
#pragma unroll
            for (int j = 0; j < 4; j++) {
                float4 v = *(const float4*)(bp + j * 4);
                const int nl = bn0 + j * 4;
                Bs[SWZ(nl + 0, bk)] = f2tf(v.x);
                Bs[SWZ(nl + 1, bk)] = f2tf(v.y);
                Bs[SWZ(nl + 2, bk)] = f2tf(v.z);
                Bs[SWZ(nl + 3, bk)] = f2tf(v.w);
            }
        } else {
            // B[n][k] (K contig). NT == 64.
            const int br = tid >> 2;           // 0..63
            const int bq = (tid & 3) << 3;     // 0,8,16,24
            const float* bp = B + (size_t)br * ldb + k0 + bq;
#pragma unroll
            for (int j = 0; j < 2; j++) {
                float4 v = *(const float4*)(bp + j * 4);
                uint4 u;
                u.x = f2tf(v.x); u.y = f2tf(v.y); u.z = f2tf(v.z); u.w = f2tf(v.w);
                *(uint4*)&Bs[SWZ(br, bq + j * 4)] = u;
            }
        }

        __syncthreads();

        // ---- compute: 4 k-steps of 8 ----
#pragma unroll
        for (int ks = 0; ks < 4; ks++) {
            const int kk = ks << 3;
            uint32_t af[MT][4];
#pragma unroll
            for (int mt = 0; mt < MT; mt++) {
                const int r = mBase + mt * 16 + gid;
                af[mt][0] = As[SWZ(r,     kk + tig)];
                af[mt][1] = As[SWZ(r + 8, kk + tig)];
                af[mt][2] = As[SWZ(r,     kk + tig + 4)];
                af[mt][3] = As[SWZ(r + 8, kk + tig + 4)];
            }
#pragma unroll
            for (int nt = 0; nt < 8; nt++) {
                const int cc = nBase + nt * 8 + gid;
                const uint32_t b0 = Bs[SWZ(cc, kk + tig)];
                const uint32_t b1 = Bs[SWZ(cc, kk + tig + 4)];
#pragma unroll
                for (int mt = 0; mt < MT; mt++)
                    mma8(acc[mt][nt], af[mt], b0, b1);
            }
        }
        __syncthreads();
    }

    // ---- epilogue ----
#pragma unroll
    for (int mt = 0; mt < MT; mt++) {
#pragma unroll
        for (int nt = 0; nt < 8; nt++) {
            const int row = m0 + mBase + mt * 16 + gid;
            const int col = n0 + nBase + nt * 8 + tig * 2;
            const float* a = acc[mt][nt];
#pragma unroll
            for (int h = 0; h < 2; h++) {
                const int r = row + h * 8;
                if (r < Mtot) {
                    const float bi = bias ? bias[r] : 0.0f;
                    float2 o;
                    o.x = a[h * 2 + 0] + bi;
                    o.y = a[h * 2 + 1] + bi;
                    if (EPI == 0) {
                        *(float2*)(C + (size_t)r * ldc + col) = o;
                    } else {
                        float* cp = C + (size_t)(col >> 6) * (DM * S_)
                                      + (size_t)r * S_ + (col & 63);
                        *(float2*)cp = o;
                    }
                }
            }
        }
    }
}

// ---------------------------------------------------------------------------
// Reduce split-K partials: hcb = sum of KSPLIT3 slabs of [512,2048]
// ---------------------------------------------------------------------------
__global__ void __launch_bounds__(256) reduce_splitk(
    const float4* __restrict__ in, float4* __restrict__ out)
{
    const int n4 = (DM * B_ * S_) / 4;  // 262144
    const int i = blockIdx.x * 256 + threadIdx.x;
    if (i >= n4) return;
    float4 s = in[i];
#pragma unroll
    for (int k = 1; k < KSPLIT3; k++) {
        float4 v = in[i + (size_t)k * n4];
        s.x += v.x; s.y += v.y; s.z += v.z; s.w += v.w;
    }
    out[i] = s;
}

// ---------------------------------------------------------------------------
// Fused depthwise 3x3 conv + softmax + AB. One block per (s, b).
// A[s] is constant along the softmax axis -> cancels; Bm never hits memory.
// ---------------------------------------------------------------------------
__global__ void __launch_bounds__(256) conv_softmax_ab(
    const float* __restrict__ braw,
    const float* __restrict__ w_dw, const float* __restrict__ b_dw,
    float* __restrict__ cm, float* __restrict__ ab)
{
    __shared__ float sin[4096];
    __shared__ float red[256];

    const int s  = blockIdx.x;
    const int b  = blockIdx.y;
    const int tid = threadIdx.x;
    const size_t base = (size_t)b * (3 * S_ * L_);

    float r[16], p[16], w[9];

    {   // dt channel -> softmax probs
        const int ch = 128 + s;
        const float* ip = braw + base + (size_t)ch * 4096;
        for (int k = 0; k < 16; k++) sin[tid + k * 256] = ip[tid + k * 256];
#pragma unroll
        for (int j = 0; j < 9; j++) w[j] = w_dw[ch * 9 + j];
        const float bv = b_dw[ch];
        __syncthreads();

#pragma unroll
        for (int k = 0; k < 16; k++) {
            const int idx = k * 256 + tid;
            const int i = idx >> 6, j = idx & 63;
            float acc = bv;
#pragma unroll
            for (int di = 0; di < 3; di++) {
                const int ii = i + di - 1;
                if (ii < 0 || ii > 63) continue;
#pragma unroll
                for (int dj = 0; dj < 3; dj++) {
                    const int jj = j + dj - 1;
                    if (jj < 0 || jj > 63) continue;
                    acc += w[di * 3 + dj] * sin[(ii << 6) + jj];
                }
            }
            r[k] = acc;
        }
        float mx = r[0];
#pragma unroll
        for (int k = 1; k < 16; k++) mx = fmaxf(mx, r[k]);
        red[tid] = mx; __syncthreads();
        for (int off = 128; off > 0; off >>= 1) {
            if (tid < off) red[tid] = fmaxf(red[tid], red[tid + off]);
            __syncthreads();
        }
        mx = red[0]; __syncthreads();
        float sum = 0.0f;
#pragma unroll
        for (int k = 0; k < 16; k++) { p[k] = expf(r[k] - mx); sum += p[k]; }
        red[tid] = sum; __syncthreads();
        for (int off = 128; off > 0; off >>= 1) {
            if (tid < off) red[tid] += red[tid + off];
            __syncthreads();
        }
        const float inv = 1.0f / red[0];
#pragma unroll
        for (int k = 0; k < 16; k++) p[k] *= inv;
        __syncthreads();
    }

    {   // Bm channel -> AB = p * conv(Bm)
        const int ch = s;
        const float* ip = braw + base + (size_t)ch * 4096;
        for (int k = 0; k < 16; k++) sin[tid + k * 256] = ip[tid + k * 256];
#pragma unroll
        for (int j = 0; j < 9; j++) w[j] = w_dw[ch * 9 + j];
        const float bv = b_dw[ch];
        __syncthreads();

        float* op = ab + (size_t)b * (S_ * L_) + (size_t)s * 4096;
#pragma unroll
        for (int k = 0; k < 16; k++) {
            const int idx = k * 256 + tid;
            const int i = idx >> 6, j = idx & 63;
            float acc = bv;
#pragma unroll
            for (int di = 0; di < 3; di++) {
                const int ii = i + di - 1;
                if (ii < 0 || ii > 63) continue;
#pragma unroll
                for (int dj = 0; dj < 3; dj++) {
                    const int jj = j + dj - 1;
                    if (jj < 0 || jj > 63) continue;
                    acc += w[di * 3 + dj] * sin[(ii << 6) + jj];
                }
            }
            op[idx] = p[k] * acc;
        }
        __syncthreads();
    }

    {   // Cm channel -> cm
        const int ch = 64 + s;
        const float* ip = braw + base + (size_t)ch * 4096;
        for (int k = 0; k < 16; k++) sin[tid + k * 256] = ip[tid + k * 256];
#pragma unroll
        for (int j = 0; j < 9; j++) w[j] = w_dw[ch * 9 + j];
        const float bv = b_dw[ch];
        __syncthreads();

        float* op = cm + (size_t)b * (S_ * L_) + (size_t)s * 4096;
#pragma unroll
        for (int k = 0; k < 16; k++) {
            const int idx = k * 256 + tid;
            const int i = idx >> 6, j = idx & 63;
            float acc = bv;
#pragma unroll
            for (int di = 0; di < 3; di++) {
                const int ii = i + di - 1;
                if (ii < 0 || ii > 63) continue;
#pragma unroll
                for (int dj = 0; dj < 3; dj++) {
                    const int jj = j + dj - 1;
                    if (jj < 0 || jj > 63) continue;
                    acc += w[di * 3 + dj] * sin[(ii << 6) + jj];
                }
            }
            op[idx] = acc;
        }
    }
}

// Gating: hg = h1 * (z*sigmoid(z) + Dskip), layout [o][b*64+s]
__global__ void __launch_bounds__(256) gate_kernel(
    const float* __restrict__ hz, float* __restrict__ hg,
    const float* __restrict__ Dskip)
{
    const int total = DM * B_ * S_;
    const int i = blockIdx.x * 256 + threadIdx.x;
    if (i >= total) return;
    const float h1 = hz[i];
    const float z  = hz[i + total];
    const float sig = 1.0f / (1.0f + expf(-z));
    hg[i] = h1 * (z * sig + Dskip[0]);
}

// ===========================================================================
// Host launch
// ===========================================================================
extern "C" void kernel_launch(void* const* d_in, const int* in_sizes, int n_in,
                              void* d_out, int out_size)
{
    (void)in_sizes; (void)n_in; (void)out_size;

    const float* x      = (const float*)d_in[0];   // [32,512,4096]
    const float* w_bcdt = (const float*)d_in[1];   // [192,512]
    const float* b_bcdt = (const float*)d_in[2];   // [192]
    const float* w_dw   = (const float*)d_in[3];   // [192,1,3,3]
    const float* b_dw   = (const float*)d_in[4];   // [192]
    const float* w_hz   = (const float*)d_in[5];   // [1024,512]
    const float* b_hz   = (const float*)d_in[6];   // [1024]
    const float* w_out  = (const float*)d_in[7];   // [512,512]
    const float* b_out  = (const float*)d_in[8];   // [512]
    const float* Dskip  = (const float*)d_in[10];  // [1] (A at [9] cancels in softmax)

    float* out = (float*)d_out;
    float* y   = out;                               // [32,512,4096]
    float* ho  = out + (size_t)B_ * DM * L_;        // [32,512,64]

    float *braw, *cm, *ab, *hpart, *hcb, *hz, *hg;
    cudaGetSymbolAddress((void**)&braw,  g_braw);
    cudaGetSymbolAddress((void**)&cm,    g_cm);
    cudaGetSymbolAddress((void**)&ab,    g_ab);
    cudaGetSymbolAddress((void**)&hpart, g_hpart);
    cudaGetSymbolAddress((void**)&hcb,   g_hcb);
    cudaGetSymbolAddress((void**)&hz,    g_hz);
    cudaGetSymbolAddress((void**)&hg,    g_hg);

    const dim3 blk(256);

    // 1) braw[b] = w_bcdt @ x[b] + b_bcdt   (M=192, N=4096, K=512)  B = x (N contig)
    gemm_mma<128, true, 1, 0><<<dim3(L_ / 128, 2, B_), blk>>>(
        w_bcdt, 0, DM,
        x, (long long)DM * L_, L_,
        braw, (long long)3 * S_ * L_, L_, 0,
        b_bcdt, 192, DM);

    // 2) fused dwconv + softmax + AB / Cm
    conv_softmax_ab<<<dim3(S_, B_), blk>>>(braw, w_dw, b_dw, cm, ab);

    // 3) hpart[kseg] = x[b] @ AB[b]^T  (M=512, N=64, K=4096, split-K=4)
    //    output into [c][b*64+s] layout: C = hpart + kseg*1048576 + bz*64
    gemm_mma<64, false, KSPLIT3, 0><<<dim3(1, DM / 128, B_ * KSPLIT3), blk>>>(
        x, (long long)DM * L_, L_,
        ab, (long long)S_ * L_, L_,
        hpart, 64, B_ * S_, (long long)DM * B_ * S_,
        nullptr, DM, L_);

    // 4) reduce partials -> hcb [512][2048]
    reduce_splitk<<<(DM * B_ * S_ / 4 + 255) / 256, blk>>>(
        (const float4*)hpart, (float4*)hcb);

    // 5) hz = w_hz @ hcb + b_hz   (M=1024, N=2048, K=512)  B = hcb (N contig)
    gemm_mma<128, true, 1, 0><<<dim3(B_ * S_ / 128, 8, 1), blk>>>(
        w_hz, 0, DM,
        hcb, 0, B_ * S_,
        hz, 0, B_ * S_, 0,
        b_hz, 2 * DM, DM);

    // 6) gating
    gate_kernel<<<(DM * B_ * S_ + 255) / 256, blk>>>(hz, hg, Dskip);

    // 7) ho = w_out @ hg + b_out, scattered into d_out [b][512][64]
    gemm_mma<128, true, 1, 1><<<dim3(B_ * S_ / 128, 4, 1), blk>>>(
        w_out, 0, DM,
        hg, 0, B_ * S_,
        ho, 0, 0, 0,
        b_out, DM, DM);

    // 8) y[b] = ho[b] @ Cm[b]   (M=512, N=4096, K=64)  B = cm (N contig)
    gemm_mma<128, true, 1, 0><<<dim3(L_ / 128, 4, B_), blk>>>(
        ho, (long long)DM * S_, S_,
        cm, (long long)S_ * L_, L_,
        y, (long long)DM * L_, L_, 0,
        nullptr, DM, S_);
}